// round 5
// baseline (speedup 1.0000x reference)
#include <cuda_runtime.h>
#include <cstdint>

// Embedding gather via TMA bulk copies (bypasses L1tex miss tracking).
// idx: [8192] int32, weight: [32000, 512] f32 (2 KB/row), out: [8192, 512] f32
//
// Each 32-thread CTA handles 8 consecutive tokens:
//   - coalesced idx load (lanes 0..7), values shared via shfl
//   - lane 0 issues 8x cp.async.bulk g->s (2 KB each) on one mbarrier
//   - lane 0 waits mbarrier, then one 16 KB cp.async.bulk s->g store
//     (output rows for consecutive tokens are contiguous)

static constexpr int ROW_BYTES      = 2048;   // 512 f32
static constexpr int TOKENS_PER_CTA = 8;
static constexpr int THREADS        = 32;
static constexpr int TILE_BYTES     = TOKENS_PER_CTA * ROW_BYTES; // 16 KB

__global__ void __launch_bounds__(THREADS, 1)
embedding_tma_kernel(const int* __restrict__ idx,
                     const char* __restrict__ weight,
                     char* __restrict__ out)
{
    __shared__ alignas(128) char buf[TILE_BYTES];
    __shared__ alignas(8) uint64_t mbar;

    const int lane       = threadIdx.x;
    const int base_token = blockIdx.x * TOKENS_PER_CTA;

    // Coalesced index load; broadcast via shuffle below.
    int row = 0;
    if (lane < TOKENS_PER_CTA)
        row = __ldg(&idx[base_token + lane]);

    const uint32_t smem_buf = (uint32_t)__cvta_generic_to_shared(buf);
    const uint32_t smem_bar = (uint32_t)__cvta_generic_to_shared(&mbar);

    if (lane == 0) {
        asm volatile("mbarrier.init.shared.b64 [%0], 1;" :: "r"(smem_bar) : "memory");
        asm volatile("fence.proxy.async.shared::cta;" ::: "memory");
        asm volatile("mbarrier.arrive.expect_tx.shared.b64 _, [%0], %1;"
                     :: "r"(smem_bar), "r"((uint32_t)TILE_BYTES) : "memory");
    }

    // Issue 8 independent 2 KB bulk gathers (lane 0 only; rows via shfl).
#pragma unroll
    for (int k = 0; k < TOKENS_PER_CTA; k++) {
        const int r = __shfl_sync(0xFFFFFFFF, row, k);
        if (lane == 0) {
            const char* src = weight + (long long)r * ROW_BYTES;
            asm volatile(
                "cp.async.bulk.shared::cta.global.mbarrier::complete_tx::bytes "
                "[%0], [%1], %2, [%3];"
                :: "r"(smem_buf + k * ROW_BYTES), "l"(src),
                   "r"((uint32_t)ROW_BYTES), "r"(smem_bar)
                : "memory");
        }
    }

    if (lane == 0) {
        // Wait for all 16 KB to land (phase parity 0).
        uint32_t done = 0;
        while (!done) {
            asm volatile(
                "{\n\t"
                ".reg .pred p;\n\t"
                "mbarrier.try_wait.parity.shared::cta.b64 p, [%1], %2, 0x989680;\n\t"
                "selp.b32 %0, 1, 0, p;\n\t"
                "}"
                : "=r"(done) : "r"(smem_bar), "r"(0u) : "memory");
        }

        // Contiguous 16 KB bulk store to out[base_token ...].
        char* dst = out + (long long)base_token * ROW_BYTES;
        asm volatile(
            "cp.async.bulk.global.shared::cta.bulk_group [%0], [%1], %2;"
            :: "l"(dst), "r"(smem_buf), "r"((uint32_t)TILE_BYTES)
            : "memory");
        asm volatile("cp.async.bulk.commit_group;" ::: "memory");
        asm volatile("cp.async.bulk.wait_group 0;" ::: "memory");
    }
}

extern "C" void kernel_launch(void* const* d_in, const int* in_sizes, int n_in,
                              void* d_out, int out_size)
{
    const int*  idx    = (const int*)d_in[0];     // x: [4, 2048] int32
    const char* weight = (const char*)d_in[1];    // [32000, 512] f32
    char*       out    = (char*)d_out;            // [4, 2048, 512] f32

    const int n_tokens = in_sizes[0];             // 8192
    const int n_ctas   = n_tokens / TOKENS_PER_CTA; // 1024

    embedding_tma_kernel<<<n_ctas, THREADS>>>(idx, weight, out);
}